// round 5
// baseline (speedup 1.0000x reference)
#include <cuda_runtime.h>
#include <cuda_bf16.h>
#include <math.h>
#include <stdint.h>

// DelayAndSum: out[b,t] = (1/128) * sum_s x[b, t+d_s, s], zero past T.
// d_s = rint(s*sin(0.5235987755982988)/2) in [0,32].
//
// SMEM-free streaming design: one warp per 256-output item. Warp streams
// rows t = o0 .. o0+287; lane m loads float4 (sensors 4m..4m+3) of each row
// (warp = one contiguous 512B row -> perfect coalescing). Per row, lane m
// forms a_m (elems with d==m -> out[t-m]) and c_m (d==m+1 -> out[t-m-1]).
// A 32-slot register ring (lane m owns out index == m mod 32) is fed via two
// shfl.idx; the wrapping lane closes out[t-32] and restarts with a_0.
// Completed outputs are contiguous per 32-row block -> coalesced STG.
//
// O_OUT=256 (vs 512 in R4) doubles grid warps to 6256 (~42/SM): occupancy
// was grid-limited at 21 warps/SM; extra halo traffic (+6%) is paid for by
// latency hiding.

#define O_OUT    256
#define NTHREADS 256

__global__ __launch_bounds__(NTHREADS)
void das3_kernel(const float* __restrict__ x, float* __restrict__ out,
                 int T, int itemsPerBatch, int nItems, uint4 cmask)
{
    const int gw = (blockIdx.x * NTHREADS + threadIdx.x) >> 5;
    const int m  = threadIdx.x & 31;
    if (gw >= nItems) return;

    const int b  = gw / itemsPerBatch;
    const int o0 = (gw % itemsPerBatch) * O_OUT;   // multiple of 32

    const float* __restrict__ xb = x + (size_t)b * (size_t)T * 128 + 4 * m;
    float* __restrict__ outb = out + (size_t)b * T;

    // per-lane split mask: bit j set <=> d(4m+j) == m (goes to a), else d==m+1 (c)
    uint32_t mword = (m < 8)  ? cmask.x :
                     (m < 16) ? cmask.y :
                     (m < 24) ? cmask.z : cmask.w;
    uint32_t bits = (mword >> ((m & 7) * 4)) & 0xFu;
    const float f0 = (bits & 1u) ? 1.f : 0.f;
    const float f1 = (bits & 2u) ? 1.f : 0.f;
    const float f2 = (bits & 4u) ? 1.f : 0.f;
    const float f3 = (bits & 8u) ? 1.f : 0.f;

    const bool full = (o0 + O_OUT + 32 <= T);

    float acc = 0.f, fin = 0.f;

    #pragma unroll 1
    for (int blk = 0; blk <= O_OUT / 32; ++blk) {
        const int t_base = o0 + blk * 32;          // multiple of 32

        if (full) {
            #pragma unroll 8
            for (int k = 0; k < 32; ++k) {
                const int t = t_base + k;
                float4 v = *(const float4*)(xb + (size_t)t * 128);
                float tot = (v.x + v.y) + (v.z + v.w);
                float a = fmaf(v.x, f0, fmaf(v.y, f1, fmaf(v.z, f2, v.w * f3)));
                float c = tot - a;
                int r = (k - m) & 31;
                float u1 = __shfl_sync(0xffffffffu, a, r);
                float u2 = __shfl_sync(0xffffffffu, c, (r + 31) & 31);
                bool wrap = (r == 0);
                float closed = acc + u2;
                fin = wrap ? closed : fin;
                acc = wrap ? u1 : acc + (u1 + u2);
            }
        } else {
            #pragma unroll 8
            for (int k = 0; k < 32; ++k) {
                const int t = t_base + k;
                float4 v = make_float4(0.f, 0.f, 0.f, 0.f);
                if (t < T) v = *(const float4*)(xb + (size_t)t * 128);
                float tot = (v.x + v.y) + (v.z + v.w);
                float a = fmaf(v.x, f0, fmaf(v.y, f1, fmaf(v.z, f2, v.w * f3)));
                float c = tot - a;
                int r = (k - m) & 31;
                float u1 = __shfl_sync(0xffffffffu, a, r);
                float u2 = __shfl_sync(0xffffffffu, c, (r + 31) & 31);
                bool wrap = (r == 0);
                float closed = acc + u2;
                fin = wrap ? closed : fin;
                acc = wrap ? u1 : acc + (u1 + u2);
            }
        }

        if (blk > 0) {
            int o = t_base - 32 + m;               // contiguous across lanes
            if (o < T) outb[o] = fin * (1.0f / 128.0f);
        }
    }
}

extern "C" void kernel_launch(void* const* d_in, const int* in_sizes, int n_in,
                              void* d_out, int out_size)
{
    const float* x = (const float*)d_in[0];
    float* out = (float*)d_out;

    const int T = 100000;
    const int B = out_size / T;                    // 16

    // Host-side delay split mask (same libm as numpy's round path).
    double q = sin(0.5235987755982988);
    uint32_t cm[4] = {0u, 0u, 0u, 0u};
    for (int l = 0; l < 32; ++l) {
        uint32_t nib = 0u;
        for (int j = 0; j < 4; ++j) {
            int s = 4 * l + j;
            int d = (int)rint((double)s * q / 2.0);
            if (d == l) nib |= (1u << j);
        }
        cm[l >> 3] |= nib << ((l & 7) * 4);
    }
    uint4 cmask = make_uint4(cm[0], cm[1], cm[2], cm[3]);

    const int itemsPerBatch = (T + O_OUT - 1) / O_OUT;   // 391
    const int nItems = B * itemsPerBatch;                // 6256 warps
    const int nThreadsTotal = nItems * 32;
    const int grid = (nThreadsTotal + NTHREADS - 1) / NTHREADS;  // 782 CTAs

    das3_kernel<<<grid, NTHREADS>>>(x, out, T, itemsPerBatch, nItems, cmask);
}

// round 6
// speedup vs baseline: 1.0872x; 1.0872x over previous
#include <cuda_runtime.h>
#include <cuda_bf16.h>
#include <math.h>
#include <stdint.h>

// DelayAndSum: out[b,t] = (1/128) * sum_s x[b, t+d_s, s], zero past T.
// d_s = rint(s*sin(0.5235987755982988)/2) in [0,32].
//
// Streaming warp-ring design (see R4) with:
//  - O_OUT=672 -> 2384 warps (~16 streams/SM; DRAM row locality favors few
//    long streams; R5 showed 37/SM regresses)
//  - explicit double-buffered 8-row prefetch: two 4KB sequential bursts per
//    stream always in flight; buffer parity is compile-time (unrolled groups)
//  - grid = 298 CTAs: max 2 CTAs/SM vs avg 2.01 -> ~zero imbalance tail.

#define O_OUT    672
#define NB       (O_OUT / 32)     // 21 blocks
#define NTHREADS 256

__global__ __launch_bounds__(NTHREADS)
void das4_kernel(const float* __restrict__ x, float* __restrict__ out,
                 int T, int itemsPerBatch, int nItems, uint4 cmask)
{
    const int gw = (blockIdx.x * NTHREADS + threadIdx.x) >> 5;
    const int m  = threadIdx.x & 31;
    if (gw >= nItems) return;

    const int b  = gw / itemsPerBatch;
    const int o0 = (gw % itemsPerBatch) * O_OUT;   // multiple of 32

    const float* __restrict__ xb = x + (size_t)b * (size_t)T * 128 + 4 * m;
    float* __restrict__ outb = out + (size_t)b * T;

    // per-lane split mask: bit j set <=> d(4m+j) == m (row t+m), else d==m+1
    uint32_t mword = (m < 8)  ? cmask.x :
                     (m < 16) ? cmask.y :
                     (m < 24) ? cmask.z : cmask.w;
    uint32_t bits = (mword >> ((m & 7) * 4)) & 0xFu;
    const float f0 = (bits & 1u) ? 1.f : 0.f;
    const float f1 = (bits & 2u) ? 1.f : 0.f;
    const float f2 = (bits & 4u) ? 1.f : 0.f;
    const float f3 = (bits & 8u) ? 1.f : 0.f;

    float acc = 0.f, fin = 0.f;

    if (o0 + O_OUT + 32 <= T) {
        // ---------- full interior item: double-buffered prefetch ----------
        const int ROWS_TOT = (NB + 1) * 32;        // 704
        float4 buf0[8], buf1[8];

        #pragma unroll
        for (int i = 0; i < 8; ++i)
            buf0[i] = *(const float4*)(xb + (size_t)(o0 + i) * 128);

        #pragma unroll 1
        for (int blk = 0; blk <= NB; ++blk) {
            #pragma unroll
            for (int g = 0; g < 4; ++g) {
                const int nextbase = blk * 32 + g * 8 + 8;
                float4* cur = (g & 1) ? buf1 : buf0;
                float4* nxt = (g & 1) ? buf0 : buf1;
                if (nextbase < ROWS_TOT) {
                    #pragma unroll
                    for (int i = 0; i < 8; ++i)
                        nxt[i] = *(const float4*)
                                 (xb + (size_t)(o0 + nextbase + i) * 128);
                }
                #pragma unroll
                for (int kk = 0; kk < 8; ++kk) {
                    const int k = g * 8 + kk;      // 0..31 within block
                    float4 v = cur[kk];
                    float tot = (v.x + v.y) + (v.z + v.w);
                    float a = fmaf(v.x, f0,
                               fmaf(v.y, f1, fmaf(v.z, f2, v.w * f3)));
                    float c = tot - a;
                    int r = (k - m) & 31;
                    float u1 = __shfl_sync(0xffffffffu, a, r);
                    float u2 = __shfl_sync(0xffffffffu, c, (r + 31) & 31);
                    bool wrap = (r == 0);
                    float closed = acc + u2;
                    fin = wrap ? closed : fin;
                    acc = wrap ? u1 : acc + (u1 + u2);
                }
            }
            if (blk > 0)
                outb[o0 + (blk - 1) * 32 + m] = fin * (1.0f / 128.0f);
        }
    } else {
        // ---------- tail item (last per batch): guarded simple path ----------
        #pragma unroll 1
        for (int blk = 0; blk <= NB; ++blk) {
            const int t_base = o0 + blk * 32;
            #pragma unroll 8
            for (int k = 0; k < 32; ++k) {
                const int t = t_base + k;
                float4 v = make_float4(0.f, 0.f, 0.f, 0.f);
                if (t < T) v = *(const float4*)(xb + (size_t)t * 128);
                float tot = (v.x + v.y) + (v.z + v.w);
                float a = fmaf(v.x, f0,
                           fmaf(v.y, f1, fmaf(v.z, f2, v.w * f3)));
                float c = tot - a;
                int r = (k - m) & 31;
                float u1 = __shfl_sync(0xffffffffu, a, r);
                float u2 = __shfl_sync(0xffffffffu, c, (r + 31) & 31);
                bool wrap = (r == 0);
                float closed = acc + u2;
                fin = wrap ? closed : fin;
                acc = wrap ? u1 : acc + (u1 + u2);
            }
            if (blk > 0) {
                int o = t_base - 32 + m;
                if (o < T) outb[o] = fin * (1.0f / 128.0f);
            }
        }
    }
}

extern "C" void kernel_launch(void* const* d_in, const int* in_sizes, int n_in,
                              void* d_out, int out_size)
{
    const float* x = (const float*)d_in[0];
    float* out = (float*)d_out;

    const int T = 100000;
    const int B = out_size / T;                    // 16

    // Host-side delay split mask (same libm as numpy's round path).
    double q = sin(0.5235987755982988);
    uint32_t cm[4] = {0u, 0u, 0u, 0u};
    for (int l = 0; l < 32; ++l) {
        uint32_t nib = 0u;
        for (int j = 0; j < 4; ++j) {
            int s = 4 * l + j;
            int d = (int)rint((double)s * q / 2.0);
            if (d == l) nib |= (1u << j);
        }
        cm[l >> 3] |= nib << ((l & 7) * 4);
    }
    uint4 cmask = make_uint4(cm[0], cm[1], cm[2], cm[3]);

    const int itemsPerBatch = (T + O_OUT - 1) / O_OUT;   // 149
    const int nItems = B * itemsPerBatch;                // 2384 warps
    const int nThreadsTotal = nItems * 32;
    const int grid = (nThreadsTotal + NTHREADS - 1) / NTHREADS;  // 298 CTAs

    das4_kernel<<<grid, NTHREADS>>>(x, out, T, itemsPerBatch, nItems, cmask);
}

// round 8
// speedup vs baseline: 1.1274x; 1.0370x over previous
#include <cuda_runtime.h>
#include <cuda_bf16.h>
#include <math.h>
#include <stdint.h>

// DelayAndSum: out[b,t] = (1/128) * sum_s x[b, t+d_s, s], zero past T.
// d_s = rint(s*sin(0.5235987755982988)/2) in [0,32].
//
// Halo-free streaming ring (R7):
//  - T = 100000 = 3125 blocks of 32 rows per batch; blocks partitioned
//    contiguously over 224 warps/batch (28 CTAs x 8 warps). 16 batches ->
//    448 CTAs (~3/SM), ~24 warps/SM (R4's BW sweet spot).
//  - Each warp streams ONLY its own rows. Ring accumulator end-state =
//    partials for its last 32 outputs; the NEXT warp's opening-block
//    closures are the complementary partials (same lane index). Exchange
//    through SMEM after __syncthreads -> no per-warp 32-row halo re-read.
//  - Only warp 7 (CTA edge) closes its boundary by streaming a guarded
//    32-row halo block (0.9% traffic vs 6% before).
//  - __ldcs/__stcs: zero-reuse streams, keep L2 clean.

#define NTHREADS 256
#define WPB      8            // warps per CTA
#define CPB      28           // CTAs per batch
#define WPBATCH  (WPB * CPB)  // 224 warps per batch
#define BPB      3125         // 32-row blocks per batch (T/32)
#define BASE_BLK (BPB / WPBATCH)       // 13
#define EXTRA    (BPB % WPBATCH)       // 213 warps get 14

__global__ __launch_bounds__(NTHREADS)
void das5_kernel(const float* __restrict__ x, float* __restrict__ out,
                 int T, uint4 cmask)
{
    __shared__ float sopen[WPB][32];

    const int w  = threadIdx.x >> 5;
    const int m  = threadIdx.x & 31;
    const int c  = blockIdx.x;
    const int b  = c / CPB;
    const int cb = c % CPB;
    const int wb = cb * WPB + w;                 // warp index within batch

    const int start_blk = wb * BASE_BLK + (wb < EXTRA ? wb : EXTRA);
    const int nblk      = BASE_BLK + (wb < EXTRA ? 1 : 0);
    const int t0 = start_blk * 32;
    const int t1 = t0 + nblk * 32;

    const float* __restrict__ xb = x + (size_t)b * (size_t)T * 128 + 4 * m;
    float* __restrict__ outb = out + (size_t)b * T;

    // per-lane split mask: bit j set <=> d(4m+j) == m (row t+m), else d==m+1
    uint32_t mword = (m < 8)  ? cmask.x :
                     (m < 16) ? cmask.y :
                     (m < 24) ? cmask.z : cmask.w;
    uint32_t bits = (mword >> ((m & 7) * 4)) & 0xFu;
    const float f0 = (bits & 1u) ? 1.f : 0.f;
    const float f1 = (bits & 2u) ? 1.f : 0.f;
    const float f2 = (bits & 4u) ? 1.f : 0.f;
    const float f3 = (bits & 8u) ? 1.f : 0.f;

    const float inv = 1.0f / 128.0f;

    float acc = 0.f, fin = 0.f, open_fin = 0.f;

    // ---- main stream over own rows only (all rows < T by construction) ----
    #pragma unroll 1
    for (int blk = 0; blk < nblk; ++blk) {
        const int t_base = t0 + blk * 32;
        #pragma unroll 8
        for (int k = 0; k < 32; ++k) {
            float4 v = __ldcs((const float4*)(xb + (size_t)(t_base + k) * 128));
            float tot = (v.x + v.y) + (v.z + v.w);
            float a = fmaf(v.x, f0, fmaf(v.y, f1, fmaf(v.z, f2, v.w * f3)));
            float cc = tot - a;
            int r = (k - m) & 31;
            float u1 = __shfl_sync(0xffffffffu, a, r);
            float u2 = __shfl_sync(0xffffffffu, cc, (r + 31) & 31);
            bool wrap = (r == 0);
            float closed = acc + u2;
            fin = wrap ? closed : fin;
            acc = wrap ? u1 : acc + (u1 + u2);
        }
        if (blk == 0)
            open_fin = fin;          // partials for outputs [t0-32, t0-1]
        else
            __stcs(&outb[t_base - 32 + m], fin * inv);   // outputs closed here
    }
    // acc now holds partials for outputs [t1-32, t1-1] (lane m -> t1-32+m)

    // publish opening partials for the previous warp in this CTA
    sopen[w][m] = open_fin;

    if (w == WPB - 1) {
        // CTA-edge warp: close own boundary with a guarded 32-row halo block
        #pragma unroll 8
        for (int k = 0; k < 32; ++k) {
            const int t = t1 + k;
            float4 v = make_float4(0.f, 0.f, 0.f, 0.f);
            if (t < T) v = __ldcs((const float4*)(xb + (size_t)t * 128));
            float tot = (v.x + v.y) + (v.z + v.w);
            float a = fmaf(v.x, f0, fmaf(v.y, f1, fmaf(v.z, f2, v.w * f3)));
            float cc = tot - a;
            int r = (k - m) & 31;
            float u1 = __shfl_sync(0xffffffffu, a, r);
            float u2 = __shfl_sync(0xffffffffu, cc, (r + 31) & 31);
            bool wrap = (r == 0);
            float closed = acc + u2;
            fin = wrap ? closed : fin;
            acc = wrap ? u1 : acc + (u1 + u2);
        }
        __stcs(&outb[t1 - 32 + m], fin * inv);
    }

    __syncthreads();

    if (w < WPB - 1) {
        // complete boundary outputs with next warp's opening partials
        float final = acc + sopen[w + 1][m];
        __stcs(&outb[t1 - 32 + m], final * inv);
    }
}

extern "C" void kernel_launch(void* const* d_in, const int* in_sizes, int n_in,
                              void* d_out, int out_size)
{
    const float* x = (const float*)d_in[0];
    float* out = (float*)d_out;

    const int T = 100000;
    const int B = out_size / T;                    // 16

    // Host-side delay split mask (same libm as numpy's round path).
    double q = sin(0.5235987755982988);
    uint32_t cm[4] = {0u, 0u, 0u, 0u};
    for (int l = 0; l < 32; ++l) {
        uint32_t nib = 0u;
        for (int j = 0; j < 4; ++j) {
            int s = 4 * l + j;
            int d = (int)rint((double)s * q / 2.0);
            if (d == l) nib |= (1u << j);
        }
        cm[l >> 3] |= nib << ((l & 7) * 4);
    }
    uint4 cmask = make_uint4(cm[0], cm[1], cm[2], cm[3]);

    const int grid = B * CPB;                      // 448 CTAs
    das5_kernel<<<grid, NTHREADS>>>(x, out, T, cmask);
}

// round 9
// speedup vs baseline: 1.4017x; 1.2433x over previous
#include <cuda_runtime.h>
#include <cuda_bf16.h>
#include <math.h>
#include <stdint.h>

// DelayAndSum: out[b,t] = (1/128) * sum_s x[b, t+d_s, s], zero past T.
// d_s = rint(s*sin(0.5235987755982988)/2) in [0,32].
//
// R9: bulk-copy streaming. Each warp owns a contiguous run of 32-row blocks
// within one batch. Global reads happen ONLY via cp.async.bulk (UBLKCP):
// 8 KB (16-row) contiguous chunks into a private 3-stage SMEM ring, mbarrier
// completion, ~24 KB in flight per warp. Compute = proven ring accumulator
// (R4/R7) reading rows from SMEM (conflict-free LDS.128). Warp boundaries
// close via SMEM partial exchange; CTA-edge warp does a guarded global halo.
// 8 warps/CTA, 192 KB stages -> 1 CTA/SM, 144 CTAs (9 per batch).

#define NTHREADS  256
#define WPB       8
#define CPB       9                   // CTAs per batch
#define WPBATCH   (WPB * CPB)         // 72
#define BPB       3125                // 32-row blocks per batch (T/32)
#define BASE_BLK  (BPB / WPBATCH)     // 43
#define EXTRA     (BPB % WPBATCH)     // 29
#define CHROWS    16
#define CHBYTES   (CHROWS * 512)      // 8192
#define NSTAGE    3

#define SM_STAGES   0
#define SM_SOPEN    (WPB * NSTAGE * CHBYTES)          // 196608
#define SM_MBAR     (SM_SOPEN + WPB * 32 * 4)         // 197632
#define SM_TOTAL    (SM_MBAR + WPB * NSTAGE * 8)      // 197824

__device__ __forceinline__ void mbar_wait(uint32_t mbar, uint32_t phase) {
    asm volatile(
        "{\n\t"
        ".reg .pred P1;\n\t"
        "WAIT_LOOP_%=:\n\t"
        "mbarrier.try_wait.parity.acquire.cta.shared::cta.b64 P1, [%0], %1, 0x989680;\n\t"
        "@P1 bra.uni WAIT_DONE_%=;\n\t"
        "bra.uni WAIT_LOOP_%=;\n\t"
        "WAIT_DONE_%=:\n\t"
        "}"
        :: "r"(mbar), "r"(phase) : "memory");
}

__global__ __launch_bounds__(NTHREADS, 1)
void das6_kernel(const float* __restrict__ x, float* __restrict__ out,
                 int T, uint4 cmask)
{
    extern __shared__ char smem[];
    const uint32_t smem_u32 =
        (uint32_t)__cvta_generic_to_shared(smem);

    const int w  = threadIdx.x >> 5;
    const int m  = threadIdx.x & 31;
    const int c  = blockIdx.x;
    const int b  = c / CPB;
    const int cb = c % CPB;
    const int wb = cb * WPB + w;

    const int start_blk = wb * BASE_BLK + (wb < EXTRA ? wb : EXTRA);
    const int nblk      = BASE_BLK + (wb < EXTRA ? 1 : 0);
    const int t0  = start_blk * 32;
    const int t1  = t0 + nblk * 32;
    const int nch = nblk * 2;                     // 16-row chunks

    const float* __restrict__ xb = x + (size_t)b * (size_t)T * 128;
    float* __restrict__ outb = out + (size_t)b * T;
    float* sopen = (float*)(smem + SM_SOPEN);

    const uint32_t mbar0 = smem_u32 + SM_MBAR + w * (NSTAGE * 8);
    const uint32_t stg0  = smem_u32 + SM_STAGES + w * (NSTAGE * CHBYTES);

    // per-lane split mask: bit j set <=> d(4m+j) == m (row t+m), else d==m+1
    uint32_t mword = (m < 8)  ? cmask.x :
                     (m < 16) ? cmask.y :
                     (m < 24) ? cmask.z : cmask.w;
    uint32_t bits = (mword >> ((m & 7) * 4)) & 0xFu;
    const float f0 = (bits & 1u) ? 1.f : 0.f;
    const float f1 = (bits & 2u) ? 1.f : 0.f;
    const float f2 = (bits & 4u) ? 1.f : 0.f;
    const float f3 = (bits & 8u) ? 1.f : 0.f;
    const float inv = 1.0f / 128.0f;

    // init this warp's mbarriers
    if (m == 0) {
        #pragma unroll
        for (int s = 0; s < NSTAGE; ++s)
            asm volatile("mbarrier.init.shared.b64 [%0], %1;"
                         :: "r"(mbar0 + s * 8), "r"(1) : "memory");
    }
    __syncwarp();

    // prologue: fill the 3-stage pipeline
    if (m == 0) {
        #pragma unroll
        for (int h = 0; h < NSTAGE; ++h) {
            uint32_t bar = mbar0 + h * 8;
            uint32_t dst = stg0 + h * CHBYTES;
            const void* src = (const void*)(xb + (size_t)(t0 + h * CHROWS) * 128);
            asm volatile("mbarrier.arrive.expect_tx.shared.b64 _, [%0], %1;"
                         :: "r"(bar), "r"(CHBYTES) : "memory");
            asm volatile(
                "cp.async.bulk.shared::cluster.global.mbarrier::complete_tx::bytes "
                "[%0], [%1], %2, [%3];"
                :: "r"(dst), "l"(src), "r"(CHBYTES), "r"(bar) : "memory");
        }
    }

    float acc = 0.f, fin = 0.f, open_fin = 0.f;

    #pragma unroll 1
    for (int h = 0; h < nch; ++h) {
        const int s  = h % NSTAGE;
        const uint32_t ph = (uint32_t)((h / NSTAGE) & 1);
        mbar_wait(mbar0 + s * 8, ph);

        const float4* sb = (const float4*)(smem + w * (NSTAGE * CHBYTES)
                                                + s * CHBYTES) + m;
        const int kbase = (h & 1) << 4;
        #pragma unroll
        for (int i = 0; i < CHROWS; ++i) {
            float4 v = sb[i * 32];
            float tot = (v.x + v.y) + (v.z + v.w);
            float a = fmaf(v.x, f0, fmaf(v.y, f1, fmaf(v.z, f2, v.w * f3)));
            float cc = tot - a;
            int k = kbase + i;
            int r = (k - m) & 31;
            float u1 = __shfl_sync(0xffffffffu, a, r);
            float u2 = __shfl_sync(0xffffffffu, cc, (r + 31) & 31);
            bool wrap = (r == 0);
            float closed = acc + u2;
            fin = wrap ? closed : fin;
            acc = wrap ? u1 : acc + (u1 + u2);
        }
        __syncwarp();

        // reuse this stage for chunk h+3
        if (h + NSTAGE < nch && m == 0) {
            asm volatile("fence.proxy.async.shared::cta;" ::: "memory");
            uint32_t bar = mbar0 + s * 8;
            uint32_t dst = stg0 + s * CHBYTES;
            const void* src =
                (const void*)(xb + (size_t)(t0 + (h + NSTAGE) * CHROWS) * 128);
            asm volatile("mbarrier.arrive.expect_tx.shared.b64 _, [%0], %1;"
                         :: "r"(bar), "r"(CHBYTES) : "memory");
            asm volatile(
                "cp.async.bulk.shared::cluster.global.mbarrier::complete_tx::bytes "
                "[%0], [%1], %2, [%3];"
                :: "r"(dst), "l"(src), "r"(CHBYTES), "r"(bar) : "memory");
        }

        if (h & 1) {
            const int lb = h >> 1;
            if (lb == 0)
                open_fin = fin;      // partials for outputs [t0-32, t0-1]
            else
                outb[t0 + lb * 32 - 32 + m] = fin * inv;
        }
    }
    // acc holds partials for outputs [t1-32, t1-1] (lane m -> t1-32+m)

    sopen[w * 32 + m] = open_fin;

    if (w == WPB - 1) {
        // CTA-edge warp: close boundary via guarded global halo rows
        const float* xbl = xb + 4 * m;
        #pragma unroll 8
        for (int k = 0; k < 32; ++k) {
            const int t = t1 + k;
            float4 v = make_float4(0.f, 0.f, 0.f, 0.f);
            if (t < T) v = *(const float4*)(xbl + (size_t)t * 128);
            float tot = (v.x + v.y) + (v.z + v.w);
            float a = fmaf(v.x, f0, fmaf(v.y, f1, fmaf(v.z, f2, v.w * f3)));
            float cc = tot - a;
            int r = (k - m) & 31;
            float u1 = __shfl_sync(0xffffffffu, a, r);
            float u2 = __shfl_sync(0xffffffffu, cc, (r + 31) & 31);
            bool wrap = (r == 0);
            float closed = acc + u2;
            fin = wrap ? closed : fin;
            acc = wrap ? u1 : acc + (u1 + u2);
        }
        outb[t1 - 32 + m] = fin * inv;
    }

    __syncthreads();

    if (w < WPB - 1) {
        float final = acc + sopen[(w + 1) * 32 + m];
        outb[t1 - 32 + m] = final * inv;
    }
}

extern "C" void kernel_launch(void* const* d_in, const int* in_sizes, int n_in,
                              void* d_out, int out_size)
{
    const float* x = (const float*)d_in[0];
    float* out = (float*)d_out;

    const int T = 100000;
    const int B = out_size / T;                    // 16

    // Host-side delay split mask (same libm as numpy's round path).
    double q = sin(0.5235987755982988);
    uint32_t cm[4] = {0u, 0u, 0u, 0u};
    for (int l = 0; l < 32; ++l) {
        uint32_t nib = 0u;
        for (int j = 0; j < 4; ++j) {
            int s = 4 * l + j;
            int d = (int)rint((double)s * q / 2.0);
            if (d == l) nib |= (1u << j);
        }
        cm[l >> 3] |= nib << ((l & 7) * 4);
    }
    uint4 cmask = make_uint4(cm[0], cm[1], cm[2], cm[3]);

    static int smem_set = 0;
    if (!smem_set) {
        cudaFuncSetAttribute(das6_kernel,
                             cudaFuncAttributeMaxDynamicSharedMemorySize,
                             SM_TOTAL);
        smem_set = 1;
    }

    const int grid = B * CPB;                      // 144 CTAs
    das6_kernel<<<grid, NTHREADS, SM_TOTAL>>>(x, out, T, cmask);
}